// round 1
// baseline (speedup 1.0000x reference)
#include <cuda_runtime.h>

#define NQ     14
#define DIM    16384
#define NL     6
#define NTHR   512

// XOR swizzle so that every pass's lane-varying bits land in the low 5 slot
// bits -> conflict-free LDS.64/STS.64 in all access patterns.
__device__ __forceinline__ int slot(int i) { return i ^ ((i >> 5) & 31); }

// Apply RX pairing on local register bit MASK (compile-time after unroll).
// RX = [[c, -i s], [-i s, c]]:
//   new0 = c*a0 - i*s*a1 ; new1 = c*a1 - i*s*a0
#define GATE_PAIRS(MASK, C, S)                                          \
    _Pragma("unroll")                                                   \
    for (int k = 0; k < 32; ++k) {                                      \
        if (!(k & (MASK))) {                                            \
            const int k1 = k | (MASK);                                  \
            float2 a0 = v[k], a1 = v[k1];                               \
            v[k]  = make_float2(fmaf((C), a0.x,  (S) * a1.y),           \
                                fmaf((C), a0.y, -(S) * a1.x));          \
            v[k1] = make_float2(fmaf((C), a1.x,  (S) * a0.y),           \
                                fmaf((C), a1.y, -(S) * a0.x));          \
        }                                                               \
    }

__global__ void __launch_bounds__(NTHR, 1)
qlayer_kernel(const float* __restrict__ x,
              const float* __restrict__ params,
              float* __restrict__ out)
{
    extern __shared__ float2 st[];              // DIM amplitudes (128 KB)
    __shared__ float gc[NL * NQ];
    __shared__ float gs[NL * NQ];
    __shared__ float red[NQ];

    const int b   = blockIdx.x;
    const int tid = threadIdx.x;

    // Gate angles are shared across the batch: cos/sin once per block.
    if (tid < NL * NQ) {
        float h = 0.5f * params[tid];
        gc[tid] = cosf(h);
        gs[tid] = sinf(h);
    }
    if (tid < NQ) red[tid] = 0.0f;

    // ---------------- initial product state ----------------
    // qubit q <-> bit (13-q).  amp(i) = prod_bits(set ? sin : cos) * (-i)^popcount
    {
        float cx[NQ], sx[NQ];
#pragma unroll
        for (int q = 0; q < NQ; ++q) {
            float h = 0.5f * x[b * NQ + q];
            cx[q] = cosf(h);
            sx[q] = sinf(h);
        }
        // high 9 bits of the index come from tid (bits 5..13)
        float hm = 1.0f;
#pragma unroll
        for (int k = 0; k < 9; ++k)
            hm *= ((tid >> k) & 1) ? sx[13 - (k + 5)] : cx[13 - (k + 5)];
        const int hpop = __popc(tid);
#pragma unroll
        for (int j = 0; j < 32; ++j) {
            float m = hm;
#pragma unroll
            for (int k = 0; k < 5; ++k)
                m *= ((j >> k) & 1) ? sx[13 - k] : cx[13 - k];
            const int pop = (hpop + __popc(j)) & 3;
            float2 a;
            a.x = (pop == 0) ? m : ((pop == 2) ? -m : 0.0f);
            a.y = (pop == 3) ? m : ((pop == 1) ? -m : 0.0f);
            st[slot(tid * 32 + j)] = a;
        }
    }
    __syncthreads();

    float2 v[32];

#pragma unroll 1
    for (int l = 0; l < NL; ++l) {
        const float* lc = gc + l * NQ;
        const float* ls = gs + l * NQ;

        // ---- pass A : global bits 0..4 local (i = tid*32 + j) ----
#pragma unroll
        for (int j = 0; j < 32; ++j)
            v[j] = st[slot(tid * 32 + j)];
#pragma unroll
        for (int bb = 0; bb < 5; ++bb) {
            const float c = lc[13 - bb];         // bit bb <-> qubit 13-bb
            const float s = ls[13 - bb];
            GATE_PAIRS(1 << bb, c, s)
        }
#pragma unroll
        for (int j = 0; j < 32; ++j)
            st[slot(tid * 32 + j)] = v[j];
        __syncthreads();

        // ---- pass B : global bits 5..9 local (i = hi<<10 | j<<5 | lo) ----
        {
            const int base = ((tid >> 5) << 10) | (tid & 31);
#pragma unroll
            for (int j = 0; j < 32; ++j)
                v[j] = st[slot(base | (j << 5))];
#pragma unroll
            for (int bb = 0; bb < 5; ++bb) {
                const float c = lc[13 - (bb + 5)];
                const float s = ls[13 - (bb + 5)];
                GATE_PAIRS(1 << bb, c, s)
            }
#pragma unroll
            for (int j = 0; j < 32; ++j)
                st[slot(base | (j << 5))] = v[j];
        }
        __syncthreads();

        // ---- pass C : global bits 9..13 local (i = j<<9 | tid),
        //      gates on bits 10..13, then CNOT-ring permutation on store ----
        {
#pragma unroll
            for (int j = 0; j < 32; ++j)
                v[j] = st[slot((j << 9) | tid)];
#pragma unroll
            for (int bb = 1; bb < 5; ++bb) {     // local bit bb = global bit bb+9
                const float c = lc[13 - (bb + 9)];
                const float s = ls[13 - (bb + 9)];
                GATE_PAIRS(1 << bb, c, s)
            }
            __syncthreads();                     // stores hit other threads' slots
#pragma unroll
            for (int j = 0; j < 32; ++j) {
                const unsigned i = (unsigned)((j << 9) | tid);
                unsigned z = i ^ (i >> 1);       // suffix-XOR fold
                z ^= z >> 2;  z ^= z >> 4;  z ^= z >> 8;
                // P: bits 0..12 = suffix XOR, bit 13 = XOR of bits 0..12
                const unsigned p = (z & 0x1FFFu) |
                                   (((z ^ (i >> 13)) & 1u) << 13);
                st[slot((int)p)] = v[j];
            }
        }
        __syncthreads();
    }

    // ---------------- Z expectations ----------------
    float acc[NQ];
#pragma unroll
    for (int q = 0; q < NQ; ++q) acc[q] = 0.0f;
#pragma unroll 4
    for (int j = 0; j < 32; ++j) {
        const int i = tid * 32 + j;
        const float2 a = st[slot(i)];
        const float pr = fmaf(a.x, a.x, a.y * a.y);
#pragma unroll
        for (int q = 0; q < NQ; ++q)
            acc[q] += ((i >> (13 - q)) & 1) ? -pr : pr;
    }
    // warp reduce then block combine
#pragma unroll
    for (int q = 0; q < NQ; ++q) {
#pragma unroll
        for (int off = 16; off; off >>= 1)
            acc[q] += __shfl_xor_sync(0xffffffffu, acc[q], off);
    }
    if ((tid & 31) == 0) {
#pragma unroll
        for (int q = 0; q < NQ; ++q)
            atomicAdd(&red[q], acc[q]);
    }
    __syncthreads();
    if (tid < NQ)
        out[b * NQ + tid] = red[tid];
}

extern "C" void kernel_launch(void* const* d_in, const int* in_sizes, int n_in,
                              void* d_out, int out_size)
{
    const float* x      = (const float*)d_in[0];
    const float* params = (const float*)d_in[1];
    // defensive: x has 512*14 elements, params has 6*14
    if (n_in >= 2 && in_sizes[0] == NL * NQ) {
        const float* t = x; x = params; params = t;
    }
    float* out = (float*)d_out;

    cudaFuncSetAttribute(qlayer_kernel,
                         cudaFuncAttributeMaxDynamicSharedMemorySize,
                         DIM * (int)sizeof(float2));
    qlayer_kernel<<<512, NTHR, DIM * sizeof(float2)>>>(x, params, out);
}

// round 3
// speedup vs baseline: 1.4004x; 1.4004x over previous
#include <cuda_runtime.h>

typedef unsigned long long u64;

#define NQ     14
#define DIM    16384
#define NL     6
#define NTHR   256

// ---------------- packed f32x2 helpers (PTX-only on sm_103a) ----------------
__device__ __forceinline__ u64 pk2(float x, float y) {
    u64 r; asm("mov.b64 %0,{%1,%2};" : "=l"(r) : "f"(x), "f"(y)); return r;
}
__device__ __forceinline__ void upk2(u64 v, float& x, float& y) {
    asm("mov.b64 {%0,%1},%2;" : "=f"(x), "=f"(y) : "l"(v));
}
__device__ __forceinline__ u64 mul2(u64 a, u64 b) {
    u64 r; asm("mul.rn.f32x2 %0,%1,%2;" : "=l"(r) : "l"(a), "l"(b)); return r;
}
__device__ __forceinline__ u64 fma2(u64 a, u64 b, u64 c) {
    u64 r; asm("fma.rn.f32x2 %0,%1,%2,%3;" : "=l"(r) : "l"(a), "l"(b), "l"(c)); return r;
}
__device__ __forceinline__ u64 swap2(u64 a) {
    u64 r;
    asm("{\n\t.reg .f32 x,y;\n\tmov.b64 {x,y},%1;\n\tmov.b64 %0,{y,x};\n\t}"
        : "=l"(r) : "l"(a));
    return r;
}

// CNOT-ring permutation (GF(2)-linear): bits 0..12 = suffix-XOR, bit13 = XOR(0..12)
__device__ __forceinline__ unsigned Pfold(unsigned i) {
    unsigned z = i ^ (i >> 1);
    z ^= z >> 2; z ^= z >> 4; z ^= z >> 8;
    return (z & 0x1FFFu) | (((z ^ (i >> 13)) & 1u) << 13);
}
// float-word swizzle: XOR bits 1-5 with bits 6-10 (keeps bit0 -> LDS.64 pairs intact)
__device__ __forceinline__ unsigned ssf(unsigned w) {
    return w ^ (((w >> 6) & 31u) << 1);
}

// packed RX gate on register-index mask RM (pairs (k, k|RM), both f32x2 halves)
#define GATE2(RM, C2, S2, NS2)                                              \
    _Pragma("unroll")                                                       \
    for (int k = 0; k < 32; ++k) {                                          \
        if (!(k & (RM))) {                                                  \
            const int k1 = k | (RM);                                        \
            u64 t0 = mul2((S2),  Ri[k1]);                                   \
            u64 t1 = mul2((NS2), Rr[k1]);                                   \
            u64 t2 = mul2((S2),  Ri[k]);                                    \
            u64 t3 = mul2((NS2), Rr[k]);                                    \
            Rr[k]  = fma2((C2), Rr[k],  t0);                                \
            Ri[k]  = fma2((C2), Ri[k],  t1);                                \
            Rr[k1] = fma2((C2), Rr[k1], t2);                                \
            Ri[k1] = fma2((C2), Ri[k1], t3);                                \
        }                                                                   \
    }

__global__ void __launch_bounds__(NTHR, 1)
qlayer_kernel(const float* __restrict__ x,
              const float* __restrict__ params,
              float* __restrict__ out)
{
    extern __shared__ __align__(16) float sm[];
    float* sre = sm;            // DIM floats (real)
    float* sim = sm + DIM;      // DIM floats (imag)
    u64*   dre = (u64*)sre;     // packed pairs (bit0)
    u64*   dim_ = (u64*)sim;

    __shared__ float gc[NL * NQ];
    __shared__ float gs[NL * NQ];
    __shared__ float red[NQ];

    const int b = blockIdx.x;
    const int t = threadIdx.x;

    if (t < NL * NQ) {
        float h = 0.5f * params[t];
        gc[t] = cosf(h);
        gs[t] = sinf(h);
    }
    if (t < NQ) red[t] = 0.0f;

    // ---------------- init product state directly into registers ----------------
    // amp index i = t*64 + j ; bit bb of i <-> qubit (13-bb)
    // amp(i) = m(i) * (-i)^popcount(i)
    u64 Rr[32], Ri[32];
    {
        float cx[NQ], sx[NQ];
#pragma unroll
        for (int q = 0; q < NQ; ++q) {
            float h = 0.5f * x[b * NQ + q];
            cx[q] = cosf(h);
            sx[q] = sinf(h);
        }
        float hm = 1.0f;                      // t bit kk -> i bit 6+kk -> qubit 7-kk
#pragma unroll
        for (int kk = 0; kk < 8; ++kk)
            hm *= ((t >> kk) & 1) ? sx[7 - kk] : cx[7 - kk];
        // thread-level phase w = (-i)^(popc(t) mod 4)
        const int hp = __popc(t) & 3;
        const float wr = (hp == 0) ? 1.0f : ((hp == 2) ? -1.0f : 0.0f);
        const float wi = (hp == 3) ? 1.0f : ((hp == 1) ? -1.0f : 0.0f);
#pragma unroll
        for (int k = 0; k < 32; ++k) {
            float m5 = hm;                    // j bits 1..5 (j = 2k)
#pragma unroll
            for (int mm = 1; mm < 6; ++mm)
                m5 *= (((2 * k) >> mm) & 1) ? sx[13 - mm] : cx[13 - mm];
            float m0 = m5 * cx[13];           // j even: qubit13 bit = 0
            float m1 = m5 * sx[13];           // j odd
            // rotate w by compile-time (-i)^popc(2k)
            const int ck = __popc((unsigned)(2 * k)) & 3;
            float wkr, wki;
            if      (ck == 0) { wkr =  wr; wki =  wi; }
            else if (ck == 1) { wkr =  wi; wki = -wr; }
            else if (ck == 2) { wkr = -wr; wki = -wi; }
            else              { wkr = -wi; wki =  wr; }
            // amp0 = m0*(wkr + i*wki) ; amp1 = m1*(wkr + i*wki)*(-i) = m1*(wki - i*wkr)
            Rr[k] = pk2(m0 * wkr,  m1 * wki);
            Ri[k] = pk2(m0 * wki, -m1 * wkr);
        }
    }
    __syncthreads();

    const int lane = t & 31;
    const int hiB  = t >> 5;        // pass B: i bits 11-13
    const int midB = t & 31;        // pass B: i bits 1-5

    // pass C thread base: lane bits at i{3,4,6,7,10}, warp bits at i{5,8,9}
    const unsigned Cbase =
        ((unsigned)(lane & 1)        << 3)  |
        ((unsigned)((lane >> 1) & 1) << 4)  |
        ((unsigned)(hiB & 1)         << 5)  |
        ((unsigned)((lane >> 2) & 1) << 6)  |
        ((unsigned)((lane >> 3) & 1) << 7)  |
        ((unsigned)((hiB >> 1) & 1)  << 8)  |
        ((unsigned)((hiB >> 2) & 1)  << 9)  |
        ((unsigned)((lane >> 4) & 1) << 10);
    const unsigned hi5C   = (Cbase >> 6) & 31u;
    const unsigned dbaseC = (Cbase >> 1) ^ hi5C;   // u64-index base for pass C
    const unsigned pbC    = Pfold(Cbase);
    const unsigned spbC   = ssf(pbC);              // float-word store base (pass C)

#pragma unroll 1
    for (int l = 0; l < NL; ++l) {
        const float* lc = gc + l * NQ;
        const float* ls = gs + l * NQ;

        // ================= pass A : i = t*64 + j, gates on bits 0..5 =================
        if (l > 0) {
#pragma unroll
            for (int k = 0; k < 32; ++k) {
                int du = t * 32 + (k ^ lane);
                Rr[k] = dre[du];
                Ri[k] = dim_[du];
            }
        }
        {   // gate on bit 0 (qubit 13) — the pack bit: needs half swaps
            float c = lc[13], s = ls[13];
            u64 c2 = pk2(c, c), s2 = pk2(s, s), ns2 = pk2(-s, -s);
#pragma unroll
            for (int k = 0; k < 32; ++k) {
                u64 isw = swap2(Ri[k]);
                u64 rsw = swap2(Rr[k]);
                Rr[k] = fma2(c2, Rr[k], mul2(s2, isw));
                Ri[k] = fma2(c2, Ri[k], mul2(ns2, rsw));
            }
        }
#pragma unroll
        for (int m = 1; m < 6; ++m) {        // bits 1..5 -> qubits 12..8
            float c = lc[13 - m], s = ls[13 - m];
            u64 c2 = pk2(c, c), s2 = pk2(s, s), ns2 = pk2(-s, -s);
            const int rm = 1 << (m - 1);
            GATE2(rm, c2, s2, ns2)
        }
#pragma unroll
        for (int k = 0; k < 32; ++k) {
            int du = t * 32 + (k ^ lane);
            dre[du] = Rr[k];
            dim_[du] = Ri[k];
        }
        __syncthreads();

        // ================= pass B : k -> i bits 6..10, gates on bits 6..10 ===========
#pragma unroll
        for (int k = 0; k < 32; ++k) {
            int du = (hiB << 10) | (k << 5) | (midB ^ k);
            Rr[k] = dre[du];
            Ri[k] = dim_[du];
        }
#pragma unroll
        for (int m = 0; m < 5; ++m) {        // bits 6..10 -> qubits 7..3
            float c = lc[13 - (6 + m)], s = ls[13 - (6 + m)];
            u64 c2 = pk2(c, c), s2 = pk2(s, s), ns2 = pk2(-s, -s);
            const int rm = 1 << m;
            GATE2(rm, c2, s2, ns2)
        }
#pragma unroll
        for (int k = 0; k < 32; ++k) {
            int du = (hiB << 10) | (k << 5) | (midB ^ k);
            dre[du] = Rr[k];
            dim_[du] = Ri[k];
        }
        __syncthreads();

        // ================= pass C : k bits {0,1}->i{1,2}, {2,3,4}->i{11,12,13} =======
#pragma unroll
        for (int k = 0; k < 32; ++k) {
            unsigned du = dbaseC ^ ((unsigned)(k & 3) | ((unsigned)(k >> 2) << 10));
            Rr[k] = dre[du];
            Ri[k] = dim_[du];
        }
#pragma unroll
        for (int m = 0; m < 3; ++m) {        // bits 11..13 -> qubits 2..0
            float c = lc[13 - (11 + m)], s = ls[13 - (11 + m)];
            u64 c2 = pk2(c, c), s2 = pk2(s, s), ns2 = pk2(-s, -s);
            const int rm = 1 << (2 + m);
            GATE2(rm, c2, s2, ns2)
        }

        if (l < NL - 1) {
            __syncthreads();                 // everyone done loading before scatter
            // CNOT-ring permutation fused into the store: addr = spbC ^ const(k,b0)
#pragma unroll
            for (int k = 0; k < 32; ++k) {
                unsigned ic  = ((unsigned)(k & 3) << 1) | ((unsigned)(k >> 2) << 11);
                unsigned sc0 = ssf(Pfold(ic));              // compile-time const
                unsigned sc1 = ssf(Pfold(ic) ^ 0x2001u);    // compile-time const
                unsigned a0 = spbC ^ sc0;
                unsigned a1 = spbC ^ sc1;
                float r0, r1, i0, i1;
                upk2(Rr[k], r0, r1);
                upk2(Ri[k], i0, i1);
                sre[a0] = r0;  sim[a0] = i0;
                sre[a1] = r1;  sim[a1] = i1;
            }
            __syncthreads();
        }
    }

    // ---------------- reduction in pass-C registers (permutation via signs) ----------
    // val_q = sum_i (-1)^{bit(13-q) of P(i)} * |amp|^2 ; P(i) bit = pbC ^ const
    {
        const u64 PPc = pk2( 1.0f,  1.0f);
        const u64 MMc = pk2(-1.0f, -1.0f);
        const u64 PMc = pk2( 1.0f, -1.0f);
        const u64 MPc = pk2(-1.0f,  1.0f);
        u64 acc[NQ];
#pragma unroll
        for (int q = 0; q < NQ; ++q) acc[q] = pk2(0.0f, 0.0f);

#pragma unroll
        for (int k = 0; k < 32; ++k) {
            u64 pr2 = fma2(Rr[k], Rr[k], mul2(Ri[k], Ri[k]));  // (|a0|^2,|a1|^2)
            unsigned ic  = ((unsigned)(k & 3) << 1) | ((unsigned)(k >> 2) << 11);
            unsigned pc0 = Pfold(ic);            // compile-time
            unsigned pc1 = pc0 ^ 0x2001u;        // compile-time
#pragma unroll
            for (int q = 0; q < NQ; ++q) {
                const int bpos = 13 - q;
                const int b0b = (int)((pc0 >> bpos) & 1u);
                const int b1b = (int)((pc1 >> bpos) & 1u);
                u64 pat = b0b ? (b1b ? MMc : MPc) : (b1b ? PMc : PPc);
                acc[q] = fma2(pat, pr2, acc[q]);
            }
        }
#pragma unroll
        for (int q = 0; q < NQ; ++q) {
            float a0, a1;
            upk2(acc[q], a0, a1);
            float v = a0 + a1;
            v = ((pbC >> (13 - q)) & 1u) ? -v : v;   // thread-level sign factor
#pragma unroll
            for (int off = 16; off; off >>= 1)
                v += __shfl_xor_sync(0xffffffffu, v, off);
            if (lane == 0) atomicAdd(&red[q], v);
        }
    }
    __syncthreads();
    if (t < NQ)
        out[b * NQ + t] = red[t];
}

extern "C" void kernel_launch(void* const* d_in, const int* in_sizes, int n_in,
                              void* d_out, int out_size)
{
    const float* x      = (const float*)d_in[0];
    const float* params = (const float*)d_in[1];
    if (n_in >= 2 && in_sizes[0] == NL * NQ) {   // defensive order check
        const float* tmp = x; x = params; params = tmp;
    }
    float* out = (float*)d_out;

    cudaFuncSetAttribute(qlayer_kernel,
                         cudaFuncAttributeMaxDynamicSharedMemorySize,
                         2 * DIM * (int)sizeof(float));
    qlayer_kernel<<<512, NTHR, 2 * DIM * sizeof(float)>>>(x, params, out);
}